// round 2
// baseline (speedup 1.0000x reference)
#include <cuda_runtime.h>
#include <math.h>

// ---------------- constants ----------------
constexpr int NB   = 32;     // batch
constexpr int ND   = 512;    // d_model
constexpr int NDFF = 2048;   // d_ff
constexpr int L_E  = 512;    // encoder length
constexpr int L_D  = 592;    // decoder length (256 label + 336 pred)
constexpr int L_P  = 640;    // padded decoder length (multiple of 128)
constexpr int NC   = 7;      // channels
constexpr int NM   = 4;      // mark features
constexpr int KTOP_E = 18;   // int(3*ln(512))
constexpr int KTOP_D = 19;   // int(3*ln(592))
constexpr int PRED = 336;
constexpr int LABEL = 256;

// ---------------- static scratch ----------------
__device__ float g_X [NB*L_D*ND];
__device__ float g_A [NB*L_D*ND];
__device__ float g_Q [NB*L_P*ND];
__device__ float g_K [NB*L_P*ND];
__device__ float g_V [NB*L_P*ND];
__device__ float g_G [NB*L_P*L_P];
__device__ float g_H [NB*L_D*NDFF];
__device__ float g_E [NB*L_E*ND];
__device__ float g_TR[NB*L_D*ND];
__device__ float g_LN[NB*L_D*ND];
__device__ float g_SI[NB*L_D*NC];
__device__ float g_TI[NB*L_D*NC];
__device__ float g_MD[NB*L_D*NM];
__device__ float g_MEAN[NB*8];
__device__ float g_CORR[NB*L_P];
__device__ float g_WT[NB*24];
__device__ int   g_DLY[NB*24];
__device__ float g_CM[NB*ND];

__device__ __forceinline__ float gelu_f(float x){
    return 0.5f * x * (1.0f + erff(x * 0.7071067811865476f));
}

// ---------------- SGEMM ----------------
// C = act(A(MxK) * B + bias). transB=0: B is KxN. transB=1: B is NxK (C=A*B^T).
// Output row remap: r -> (r/Lrow)*Lpad + r%Lrow (identity when Lrow==Lpad).
// Batched via blockIdx.z with strides sA,sB,sC.
__global__ void k_gemm(const float* __restrict__ A, const float* __restrict__ Bm,
                       const float* __restrict__ bias, float* __restrict__ C,
                       int M, int N, int K, int transB, int act,
                       int Lrow, int Lpad, long sA, long sB, long sC)
{
    A  += (long)blockIdx.z * sA;
    Bm += (long)blockIdx.z * sB;
    C  += (long)blockIdx.z * sC;

    __shared__ float As[8][128];
    __shared__ float Bs[8][128];

    const int tid  = threadIdx.x;          // 256 threads
    const int row0 = blockIdx.y * 128;
    const int col0 = blockIdx.x * 128;
    const int lm = tid >> 1, lk = (tid & 1) * 4;
    const int bk = tid >> 5, bn = (tid & 31) * 4;
    const int rm = (tid >> 4) * 8, rn = (tid & 15) * 8;

    float acc[8][8];
    #pragma unroll
    for (int i = 0; i < 8; i++)
        #pragma unroll
        for (int j = 0; j < 8; j++) acc[i][j] = 0.f;

    const float* Arow  = A  + (long)(row0 + lm) * K + lk;
    const float* BrowT = Bm + (long)(col0 + lm) * K + lk;

    for (int k0 = 0; k0 < K; k0 += 8) {
        float4 a4 = *(const float4*)(Arow + k0);
        As[lk+0][lm] = a4.x; As[lk+1][lm] = a4.y;
        As[lk+2][lm] = a4.z; As[lk+3][lm] = a4.w;
        if (!transB) {
            float4 b4 = *(const float4*)(Bm + (long)(k0 + bk) * N + col0 + bn);
            *(float4*)&Bs[bk][bn] = b4;
        } else {
            float4 b4 = *(const float4*)(BrowT + k0);
            Bs[lk+0][lm] = b4.x; Bs[lk+1][lm] = b4.y;
            Bs[lk+2][lm] = b4.z; Bs[lk+3][lm] = b4.w;
        }
        __syncthreads();
        #pragma unroll
        for (int kk = 0; kk < 8; kk++) {
            float4 a0 = *(const float4*)&As[kk][rm];
            float4 a1 = *(const float4*)&As[kk][rm+4];
            float4 b0 = *(const float4*)&Bs[kk][rn];
            float4 b1 = *(const float4*)&Bs[kk][rn+4];
            float av[8] = {a0.x,a0.y,a0.z,a0.w,a1.x,a1.y,a1.z,a1.w};
            float bv[8] = {b0.x,b0.y,b0.z,b0.w,b1.x,b1.y,b1.z,b1.w};
            #pragma unroll
            for (int i = 0; i < 8; i++)
                #pragma unroll
                for (int j = 0; j < 8; j++)
                    acc[i][j] += av[i] * bv[j];
        }
        __syncthreads();
    }

    #pragma unroll
    for (int i = 0; i < 8; i++) {
        int r = row0 + rm + i;
        long outrow;
        if (Lrow != Lpad) { int bb = r / Lrow; outrow = (long)bb * Lpad + (r - bb * Lrow); }
        else outrow = r;
        float* Cp = C + outrow * (long)N + col0 + rn;
        float v[8];
        #pragma unroll
        for (int j = 0; j < 8; j++) {
            float t = acc[i][j];
            if (bias) t += bias[col0 + rn + j];
            if (act == 1) t = gelu_f(t);
            v[j] = t;
        }
        *(float4*)Cp       = make_float4(v[0], v[1], v[2], v[3]);
        *(float4*)(Cp + 4) = make_float4(v[4], v[5], v[6], v[7]);
    }
}

// circular conv (width 3, wrap) embedding + mark projection
__global__ void k_embed(const float* __restrict__ x, const float* __restrict__ mark,
                        const float* __restrict__ Wc, const float* __restrict__ Wm,
                        float* __restrict__ out, int L, long n)
{
    long i = (long)blockIdx.x * blockDim.x + threadIdx.x;
    if (i >= n) return;
    int o = (int)(i & 511);
    long bt = i >> 9;
    int t = (int)(bt % L), b = (int)(bt / L);
    int tm = (t == 0) ? (L - 1) : (t - 1);
    int tp = (t == L - 1) ? 0 : (t + 1);
    const float* xb = x + (long)b * L * NC;
    float acc = 0.f;
    #pragma unroll
    for (int c = 0; c < NC; c++) {
        acc += xb[(long)tm * NC + c] * Wc[(0*NC + c) * ND + o];
        acc += xb[(long)t  * NC + c] * Wc[(1*NC + c) * ND + o];
        acc += xb[(long)tp * NC + c] * Wc[(2*NC + c) * ND + o];
    }
    const float* mb = mark + ((long)b * L + t) * NM;
    #pragma unroll
    for (int m = 0; m < NM; m++) acc += mb[m] * Wm[m * ND + o];
    out[i] = acc;
}

__global__ void k_add(const float* __restrict__ a, const float* __restrict__ b,
                      float* __restrict__ o, long n)
{
    long i = (long)blockIdx.x * blockDim.x + threadIdx.x;
    if (i < n) o[i] = a[i] + b[i];
}

// 25-tap moving-average series decomposition with edge clamp.
// mode 0: seasonal only. 1: also store trend. 2: also accumulate trend.
__global__ void k_decomp(const float* __restrict__ in, float* __restrict__ seas,
                         float* __restrict__ trend, int L, int mode, long n)
{
    long i = (long)blockIdx.x * blockDim.x + threadIdx.x;
    if (i >= n) return;
    int d = (int)(i & 511);
    long bt = i >> 9;
    int t = (int)(bt % L), b = (int)(bt / L);
    const float* col = in + (long)b * L * ND + d;
    float s = 0.f;
    #pragma unroll
    for (int j = -12; j <= 12; j++) {
        int tt = t + j;
        tt = tt < 0 ? 0 : (tt > L - 1 ? L - 1 : tt);
        s += col[(long)tt * ND];
    }
    s *= (1.f / 25.f);
    seas[i] = in[i] - s;
    if (mode == 1)      trend[i]  = s;
    else if (mode == 2) trend[i] += s;
}

__global__ void k_zerorows(float* __restrict__ P, int r0, int r1, long n)
{
    long i = (long)blockIdx.x * blockDim.x + threadIdx.x;
    if (i >= n) return;
    int d = (int)(i & 511);
    long br = i >> 9;
    int nr = r1 - r0;
    int r = (int)(br % nr), b = (int)(br / nr);
    P[((long)b * L_P + r0 + r) * ND + d] = 0.f;
}

// corr[b,tau] = (1/512) * sum_m G[b, m, (m - tau) mod L]
__global__ void k_diag(const float* __restrict__ G, float* __restrict__ corr, int L, int Gs)
{
    int b = blockIdx.x, tau = threadIdx.x;
    if (tau >= L) return;
    const float* Gb = G + (long)b * Gs * Gs;
    float acc = 0.f;
    int s = (tau == 0) ? 0 : (L - tau);
    for (int m = 0; m < L; m++) {
        acc += Gb[(long)m * Gs + s];
        if (++s == L) s = 0;
    }
    corr[b * L_P + tau] = acc * (1.f / 512.f);
}

// per-batch top-k + softmax (first-occurrence tie-break, like lax.top_k)
__global__ void k_topk(const float* __restrict__ corr, int L, int ktop,
                       float* __restrict__ wout, int* __restrict__ dout)
{
    int b = blockIdx.x, tid = threadIdx.x;
    __shared__ float sv[L_P];
    __shared__ float rv[256];
    __shared__ int   ri[256];
    __shared__ float topv[24];
    __shared__ int   topi[24];
    for (int i = tid; i < L; i += 256) sv[i] = corr[b * L_P + i];
    __syncthreads();
    for (int kk = 0; kk < ktop; kk++) {
        float best = -1e30f; int bi = 0x7fffffff;
        for (int i = tid; i < L; i += 256) {
            float v = sv[i];
            if (v > best) { best = v; bi = i; }
        }
        rv[tid] = best; ri[tid] = bi;
        __syncthreads();
        for (int s = 128; s > 0; s >>= 1) {
            if (tid < s) {
                if (rv[tid + s] > rv[tid] ||
                    (rv[tid + s] == rv[tid] && ri[tid + s] < ri[tid])) {
                    rv[tid] = rv[tid + s]; ri[tid] = ri[tid + s];
                }
            }
            __syncthreads();
        }
        if (tid == 0) { topv[kk] = rv[0]; topi[kk] = ri[0]; sv[ri[0]] = -1e30f; }
        __syncthreads();
    }
    if (tid == 0) {
        float mx = topv[0], ssum = 0.f;
        for (int i = 0; i < ktop; i++) { float e = expf(topv[i] - mx); topv[i] = e; ssum += e; }
        float inv = 1.f / ssum;
        for (int i = 0; i < ktop; i++) { wout[b*24 + i] = topv[i]*inv; dout[b*24 + i] = topi[i]; }
    }
}

// agg[b,t,:] = sum_i w[b,i] * V[b, (t+delay[b,i]) mod L, :]
__global__ void k_agg(const float* __restrict__ V, const float* __restrict__ w,
                      const int* __restrict__ dl, int ktop, int L, int Lpad,
                      float* __restrict__ out)
{
    int b = blockIdx.x / L, t = blockIdx.x % L;
    __shared__ float sw[24];
    __shared__ int   sd[24];
    if ((int)threadIdx.x < ktop) { sw[threadIdx.x] = w[b*24 + threadIdx.x]; sd[threadIdx.x] = dl[b*24 + threadIdx.x]; }
    __syncthreads();
    const float4* Vb = (const float4*)(V + (long)b * Lpad * ND);
    float4 acc = make_float4(0.f, 0.f, 0.f, 0.f);
    for (int i = 0; i < ktop; i++) {
        int r = t + sd[i]; if (r >= L) r -= L;
        float4 v = Vb[(long)r * 128 + threadIdx.x];
        float wi = sw[i];
        acc.x += wi*v.x; acc.y += wi*v.y; acc.z += wi*v.z; acc.w += wi*v.w;
    }
    ((float4*)out)[((long)b * L + t) * 128 + threadIdx.x] = acc;
}

// layernorm over last dim (512)
__global__ void k_ln(const float* __restrict__ x, const float* __restrict__ g,
                     const float* __restrict__ be, float* __restrict__ out)
{
    long r = blockIdx.x;
    int tid = threadIdx.x;
    const float* xr = x + r * ND;
    float v0 = xr[tid], v1 = xr[tid + 256];
    __shared__ float sh[256];
    sh[tid] = v0 + v1; __syncthreads();
    for (int s = 128; s > 0; s >>= 1) { if (tid < s) sh[tid] += sh[tid + s]; __syncthreads(); }
    float mu = sh[0] * (1.f / 512.f);
    __syncthreads();
    float d0 = v0 - mu, d1 = v1 - mu;
    sh[tid] = d0*d0 + d1*d1; __syncthreads();
    for (int s = 128; s > 0; s >>= 1) { if (tid < s) sh[tid] += sh[tid + s]; __syncthreads(); }
    float rs = rsqrtf(sh[0] * (1.f / 512.f) + 1e-5f);
    out[r * ND + tid]       = d0 * rs * g[tid]       + be[tid];
    out[r * ND + tid + 256] = d1 * rs * g[tid + 256] + be[tid + 256];
}

__global__ void k_colmean(const float* __restrict__ x, float* __restrict__ cm, int L)
{
    int b = blockIdx.x;
    int d = blockIdx.y * 256 + threadIdx.x;
    const float* xb = x + (long)b * L * ND + d;
    float s = 0.f;
    for (int t = 0; t < L; t++) s += xb[(long)t * ND];
    cm[b * ND + d] = s / (float)L;
}

__global__ void k_sub(const float* __restrict__ a, const float* __restrict__ cm,
                      float* __restrict__ o, int L, long n)
{
    long i = (long)blockIdx.x * blockDim.x + threadIdx.x;
    if (i >= n) return;
    int d = (int)(i & 511);
    int b = (int)(i / ((long)L * ND));
    o[i] = a[i] - cm[b * ND + d];
}

__global__ void k_meanenc(const float* __restrict__ x, float* __restrict__ mean)
{
    int tid = threadIdx.x;
    if (tid >= NB * NC) return;
    int b = tid / NC, c = tid % NC;
    const float* xb = x + (long)b * L_E * NC + c;
    float s = 0.f;
    for (int t = 0; t < L_E; t++) s += xb[(long)t * NC];
    mean[b * 8 + c] = s * (1.f / 512.f);
}

// seasonal_init / trend_init for the decoder
__global__ void k_decinit(const float* __restrict__ x, const float* __restrict__ mean,
                          float* __restrict__ SI, float* __restrict__ TI, long n)
{
    long i = (long)blockIdx.x * blockDim.x + threadIdx.x;
    if (i >= n) return;
    int c = (int)(i % NC);
    long bt = i / NC;
    int t = (int)(bt % L_D), b = (int)(bt / L_D);
    if (t < LABEL) {
        int te = LABEL + t;
        const float* col = x + (long)b * L_E * NC + c;
        float s = 0.f;
        #pragma unroll
        for (int j = -12; j <= 12; j++) {
            int tt = te + j;
            tt = tt < 0 ? 0 : (tt > L_E - 1 ? L_E - 1 : tt);
            s += col[(long)tt * NC];
        }
        s *= (1.f / 25.f);
        TI[i] = s;
        SI[i] = col[(long)te * NC] - s;
    } else {
        TI[i] = mean[b * 8 + c];
        SI[i] = 0.f;
    }
}

__global__ void k_markdec(const float* __restrict__ me, const float* __restrict__ md,
                          float* __restrict__ out, long n)
{
    long i = (long)blockIdx.x * blockDim.x + threadIdx.x;
    if (i >= n) return;
    int m = (int)(i & 3);
    long bt = i >> 2;
    int t = (int)(bt % L_D), b = (int)(bt / L_D);
    out[i] = (t < LABEL) ? me[((long)b * L_E + LABEL + t) * NM + m]
                         : md[((long)b * PRED + (t - LABEL)) * NM + m];
}

// out = trend_init + circconv(TR, W_trend) + xln @ Wproj + bproj, last PRED steps
__global__ void k_final(const float* __restrict__ xln, const float* __restrict__ TR,
                        const float* __restrict__ TI, const float* __restrict__ Wt,
                        const float* __restrict__ Wp, const float* __restrict__ bp,
                        float* __restrict__ out, long n)
{
    long i = (long)blockIdx.x * blockDim.x + threadIdx.x;
    if (i >= n) return;
    int c = (int)(i % NC);
    long bt = i / NC;
    int t = (int)(bt % PRED), b = (int)(bt / PRED);
    int tt = LABEL + t;
    float tr = TI[((long)b * L_D + tt) * NC + c];
    #pragma unroll
    for (int w = 0; w < 3; w++) {
        int r = tt - 1 + w;
        if (r < 0) r += L_D;
        if (r >= L_D) r -= L_D;
        const float* TRr = TR + ((long)b * L_D + r) * ND;
        const float* Wtr = Wt + (long)w * ND * NC + c;
        float a = 0.f;
        for (int cc = 0; cc < ND; cc++) a += TRr[cc] * Wtr[cc * NC];
        tr += a;
    }
    float se = bp[c];
    const float* xr = xln + ((long)b * L_D + tt) * ND;
    for (int d = 0; d < ND; d++) se += xr[d] * Wp[d * NC + c];
    out[i] = tr + se;
}

static inline void launch_gemm(const float* A, const float* Bm, const float* bias, float* C,
                               int M, int N, int K, int transB, int act,
                               int Lrow, int Lpad, long sA, long sB, long sC, int batch)
{
    dim3 grid(N / 128, M / 128, batch);
    k_gemm<<<grid, 256>>>(A, Bm, bias, C, M, N, K, transB, act, Lrow, Lpad, sA, sB, sC);
}

#define FLATG(n) (int)(((n) + 255) / 256), 256

extern "C" void kernel_launch(void* const* d_in, const int* in_sizes, int n_in,
                              void* d_out, int out_size)
{
    const float* x_enc      = (const float*)d_in[0];
    const float* x_mark_enc = (const float*)d_in[1];
    const float* x_mark_dec = (const float*)d_in[3];
    const float* W_enc_emb  = (const float*)d_in[4];
    const float* W_mark_enc = (const float*)d_in[5];
    const float* W_dec_emb  = (const float*)d_in[6];
    const float* W_mark_dec = (const float*)d_in[7];
    const float* eW_attn    = (const float*)d_in[8];
    const float* eb_attn    = (const float*)d_in[9];
    const float* eW1        = (const float*)d_in[10];
    const float* eW2        = (const float*)d_in[11];
    const float* eg         = (const float*)d_in[12];
    const float* ebeta      = (const float*)d_in[13];
    const float* sW         = (const float*)d_in[14];
    const float* sb         = (const float*)d_in[15];
    const float* cW         = (const float*)d_in[16];
    const float* cb         = (const float*)d_in[17];
    const float* dW1        = (const float*)d_in[18];
    const float* dW2        = (const float*)d_in[19];
    const float* W_trend    = (const float*)d_in[20];
    const float* dg         = (const float*)d_in[21];
    const float* dbeta      = (const float*)d_in[22];
    const float* Wproj      = (const float*)d_in[23];
    const float* bproj      = (const float*)d_in[24];
    float* out = (float*)d_out;

    float *X, *A_, *Q, *Kb, *V, *G, *H, *E, *TR, *LN, *SI, *TI, *MD, *MEAN, *CORR, *WT, *CM;
    int* DLY;
    cudaGetSymbolAddress((void**)&X,   g_X);
    cudaGetSymbolAddress((void**)&A_,  g_A);
    cudaGetSymbolAddress((void**)&Q,   g_Q);
    cudaGetSymbolAddress((void**)&Kb,  g_K);
    cudaGetSymbolAddress((void**)&V,   g_V);
    cudaGetSymbolAddress((void**)&G,   g_G);
    cudaGetSymbolAddress((void**)&H,   g_H);
    cudaGetSymbolAddress((void**)&E,   g_E);
    cudaGetSymbolAddress((void**)&TR,  g_TR);
    cudaGetSymbolAddress((void**)&LN,  g_LN);
    cudaGetSymbolAddress((void**)&SI,  g_SI);
    cudaGetSymbolAddress((void**)&TI,  g_TI);
    cudaGetSymbolAddress((void**)&MD,  g_MD);
    cudaGetSymbolAddress((void**)&MEAN,g_MEAN);
    cudaGetSymbolAddress((void**)&CORR,g_CORR);
    cudaGetSymbolAddress((void**)&WT,  g_WT);
    cudaGetSymbolAddress((void**)&CM,  g_CM);
    cudaGetSymbolAddress((void**)&DLY, g_DLY);

    const long nE = (long)NB * L_E * ND;
    const long nD = (long)NB * L_D * ND;

    // ===== encoder embedding =====
    k_embed<<<FLATG(nE)>>>(x_enc, x_mark_enc, W_enc_emb, W_mark_enc, X, L_E, nE);

    // ===== encoder layers =====
    for (int l = 0; l < 2; l++) {
        const float* W  = eW_attn + (size_t)l * 4 * ND * ND;
        const float* bb = eb_attn + (size_t)l * 4 * ND;
        launch_gemm(X, W + 0*ND*ND, bb + 0*ND, Q,  NB*L_E, ND, ND, 0, 0, L_E, L_E, 0,0,0, 1);
        launch_gemm(X, W + 1*ND*ND, bb + 1*ND, Kb, NB*L_E, ND, ND, 0, 0, L_E, L_E, 0,0,0, 1);
        launch_gemm(X, W + 2*ND*ND, bb + 2*ND, V,  NB*L_E, ND, ND, 0, 0, L_E, L_E, 0,0,0, 1);
        launch_gemm(Q, Kb, nullptr, G, L_E, L_E, ND, 1, 0, L_E, L_E,
                    (long)L_E*ND, (long)L_E*ND, (long)L_E*L_E, NB);
        k_diag<<<NB, L_P>>>(G, CORR, L_E, L_E);
        k_topk<<<NB, 256>>>(CORR, L_E, KTOP_E, WT, DLY);
        k_agg<<<NB * L_E, 128>>>(V, WT, DLY, KTOP_E, L_E, L_E, A_);
        launch_gemm(A_, W + 3*ND*ND, bb + 3*ND, H, NB*L_E, ND, ND, 0, 0, L_E, L_E, 0,0,0, 1);
        k_add<<<FLATG(nE)>>>(X, H, A_, nE);
        k_decomp<<<FLATG(nE)>>>(A_, X, (float*)nullptr, L_E, 0, nE);
        launch_gemm(X, eW1 + (size_t)l*ND*NDFF,  nullptr, H,  NB*L_E, NDFF, ND,   0, 1, L_E, L_E, 0,0,0, 1);
        launch_gemm(H, eW2 + (size_t)l*NDFF*ND,  nullptr, A_, NB*L_E, ND,   NDFF, 0, 0, L_E, L_E, 0,0,0, 1);
        k_add<<<FLATG(nE)>>>(X, A_, A_, nE);
        k_decomp<<<FLATG(nE)>>>(A_, X, (float*)nullptr, L_E, 0, nE);
    }

    // ===== encoder layernorm (with time-mean subtraction) =====
    k_ln<<<NB * L_E, 256>>>(X, eg, ebeta, E);
    k_colmean<<<dim3(NB, 2), 256>>>(E, CM, L_E);
    k_sub<<<FLATG(nE)>>>(E, CM, E, L_E, nE);

    // ===== decoder init =====
    k_meanenc<<<1, 256>>>(x_enc, MEAN);
    k_decinit<<<FLATG((long)NB*L_D*NC)>>>(x_enc, MEAN, SI, TI, (long)NB*L_D*NC);
    k_markdec<<<FLATG((long)NB*L_D*NM)>>>(x_mark_enc, x_mark_dec, MD, (long)NB*L_D*NM);
    k_embed<<<FLATG(nD)>>>(SI, MD, W_dec_emb, W_mark_dec, X, L_D, nD);

    // ===== decoder self-attention =====
    launch_gemm(X, sW + 0*ND*ND, sb + 0*ND, Q,  NB*L_D, ND, ND, 0, 0, L_D, L_P, 0,0,0, 1);
    launch_gemm(X, sW + 1*ND*ND, sb + 1*ND, Kb, NB*L_D, ND, ND, 0, 0, L_D, L_P, 0,0,0, 1);
    launch_gemm(X, sW + 2*ND*ND, sb + 2*ND, V,  NB*L_D, ND, ND, 0, 0, L_D, L_P, 0,0,0, 1);
    launch_gemm(Q, Kb, nullptr, G, L_P, L_P, ND, 1, 0, L_P, L_P,
                (long)L_P*ND, (long)L_P*ND, (long)L_P*L_P, NB);
    k_diag<<<NB, L_P>>>(G, CORR, L_D, L_P);
    k_topk<<<NB, 256>>>(CORR, L_D, KTOP_D, WT, DLY);
    k_agg<<<NB * L_D, 128>>>(V, WT, DLY, KTOP_D, L_D, L_P, A_);
    launch_gemm(A_, sW + 3*ND*ND, sb + 3*ND, H, NB*L_D, ND, ND, 0, 0, L_D, L_D, 0,0,0, 1);
    k_add<<<FLATG(nD)>>>(X, H, A_, nD);
    k_decomp<<<FLATG(nD)>>>(A_, X, TR, L_D, 1, nD);

    // ===== decoder cross-attention (K/V from enc_out, zero-padded 512->592) =====
    launch_gemm(X, cW + 0*ND*ND, cb + 0*ND, Q,  NB*L_D, ND, ND, 0, 0, L_D, L_P, 0,0,0, 1);
    launch_gemm(E, cW + 1*ND*ND, cb + 1*ND, Kb, NB*L_E, ND, ND, 0, 0, L_E, L_P, 0,0,0, 1);
    launch_gemm(E, cW + 2*ND*ND, cb + 2*ND, V,  NB*L_E, ND, ND, 0, 0, L_E, L_P, 0,0,0, 1);
    {
        long nz = (long)NB * (L_D - L_E) * ND;
        k_zerorows<<<FLATG(nz)>>>(Kb, L_E, L_D, nz);
        k_zerorows<<<FLATG(nz)>>>(V,  L_E, L_D, nz);
    }
    launch_gemm(Q, Kb, nullptr, G, L_P, L_P, ND, 1, 0, L_P, L_P,
                (long)L_P*ND, (long)L_P*ND, (long)L_P*L_P, NB);
    k_diag<<<NB, L_P>>>(G, CORR, L_D, L_P);
    k_topk<<<NB, 256>>>(CORR, L_D, KTOP_D, WT, DLY);
    k_agg<<<NB * L_D, 128>>>(V, WT, DLY, KTOP_D, L_D, L_P, A_);
    launch_gemm(A_, cW + 3*ND*ND, cb + 3*ND, H, NB*L_D, ND, ND, 0, 0, L_D, L_D, 0,0,0, 1);
    k_add<<<FLATG(nD)>>>(X, H, A_, nD);
    k_decomp<<<FLATG(nD)>>>(A_, X, TR, L_D, 2, nD);

    // ===== decoder FFN =====
    launch_gemm(X, dW1, nullptr, H,  NB*L_D, NDFF, ND,   0, 1, L_D, L_D, 0,0,0, 1);
    launch_gemm(H, dW2, nullptr, A_, NB*L_D, ND,   NDFF, 0, 0, L_D, L_D, 0,0,0, 1);
    k_add<<<FLATG(nD)>>>(X, A_, A_, nD);
    k_decomp<<<FLATG(nD)>>>(A_, X, TR, L_D, 2, nD);

    // ===== decoder layernorm + final output =====
    k_ln<<<NB * L_D, 256>>>(X, dg, dbeta, LN);
    k_colmean<<<dim3(NB, 2), 256>>>(LN, CM, L_D);
    k_sub<<<FLATG(nD)>>>(LN, CM, LN, L_D, nD);

    long nOut = (long)NB * PRED * NC;
    k_final<<<FLATG(nOut)>>>(LN, TR, TI, W_trend, Wproj, bproj, out, nOut);
}

// round 3
// speedup vs baseline: 1.0018x; 1.0018x over previous
#include <cuda_runtime.h>
#include <math.h>

// ---------------- constants ----------------
constexpr int NB   = 32;     // batch
constexpr int ND   = 512;    // d_model
constexpr int NDFF = 2048;   // d_ff
constexpr int L_E  = 512;    // encoder length
constexpr int L_D  = 592;    // decoder length (256 label + 336 pred)
constexpr int L_P  = 640;    // padded decoder length (multiple of 128)
constexpr int NC   = 7;      // channels
constexpr int NM   = 4;      // mark features
constexpr int KTOP_E = 18;   // int(3*ln(512))
constexpr int KTOP_D = 19;   // int(3*ln(592))
constexpr int PRED = 336;
constexpr int LABEL = 256;

// ---------------- static scratch ----------------
__device__ float g_X [NB*L_D*ND];
__device__ float g_A [NB*L_D*ND];
__device__ float g_Q [NB*L_P*ND];
__device__ float g_K [NB*L_P*ND];
__device__ float g_V [NB*L_P*ND];
__device__ float g_G [NB*L_P*L_P];
__device__ float g_H [NB*L_D*NDFF];
__device__ float g_E [NB*L_E*ND];
__device__ float g_TR[NB*L_D*ND];
__device__ float g_LN[NB*L_D*ND];
__device__ float g_SI[NB*L_D*NC];
__device__ float g_TI[NB*L_D*NC];
__device__ float g_MD[NB*L_D*NM];
__device__ float g_MEAN[NB*8];
__device__ float g_CORR[NB*L_P];
__device__ float g_WT[NB*24];
__device__ int   g_DLY[NB*24];
__device__ float g_CM[NB*ND];

__device__ __forceinline__ float gelu_f(float x){
    return 0.5f * x * (1.0f + erff(x * 0.7071067811865476f));
}

// ---------------- SGEMM ----------------
// C = act(A(MxK) * B + bias). transB=0: B is KxN. transB=1: B is NxK (C=A*B^T).
// Output row remap: r -> (r/Lrow)*Lpad + r%Lrow (identity when Lrow==Lpad).
// Batched via blockIdx.z with strides sA,sB,sC.
__global__ void k_gemm(const float* __restrict__ A, const float* __restrict__ Bm,
                       const float* __restrict__ bias, float* __restrict__ C,
                       int M, int N, int K, int transB, int act,
                       int Lrow, int Lpad, long sA, long sB, long sC)
{
    A  += (long)blockIdx.z * sA;
    Bm += (long)blockIdx.z * sB;
    C  += (long)blockIdx.z * sC;

    __shared__ float As[8][128];
    __shared__ float Bs[8][128];

    const int tid  = threadIdx.x;          // 256 threads
    const int row0 = blockIdx.y * 128;
    const int col0 = blockIdx.x * 128;
    const int lm = tid >> 1, lk = (tid & 1) * 4;
    const int bk = tid >> 5, bn = (tid & 31) * 4;
    const int rm = (tid >> 4) * 8, rn = (tid & 15) * 8;

    float acc[8][8];
    #pragma unroll
    for (int i = 0; i < 8; i++)
        #pragma unroll
        for (int j = 0; j < 8; j++) acc[i][j] = 0.f;

    const float* Arow  = A  + (long)(row0 + lm) * K + lk;
    const float* BrowT = Bm + (long)(col0 + lm) * K + lk;

    for (int k0 = 0; k0 < K; k0 += 8) {
        float4 a4 = *(const float4*)(Arow + k0);
        As[lk+0][lm] = a4.x; As[lk+1][lm] = a4.y;
        As[lk+2][lm] = a4.z; As[lk+3][lm] = a4.w;
        if (!transB) {
            float4 b4 = *(const float4*)(Bm + (long)(k0 + bk) * N + col0 + bn);
            *(float4*)&Bs[bk][bn] = b4;
        } else {
            float4 b4 = *(const float4*)(BrowT + k0);
            Bs[lk+0][lm] = b4.x; Bs[lk+1][lm] = b4.y;
            Bs[lk+2][lm] = b4.z; Bs[lk+3][lm] = b4.w;
        }
        __syncthreads();
        #pragma unroll
        for (int kk = 0; kk < 8; kk++) {
            float4 a0 = *(const float4*)&As[kk][rm];
            float4 a1 = *(const float4*)&As[kk][rm+4];
            float4 b0 = *(const float4*)&Bs[kk][rn];
            float4 b1 = *(const float4*)&Bs[kk][rn+4];
            float av[8] = {a0.x,a0.y,a0.z,a0.w,a1.x,a1.y,a1.z,a1.w};
            float bv[8] = {b0.x,b0.y,b0.z,b0.w,b1.x,b1.y,b1.z,b1.w};
            #pragma unroll
            for (int i = 0; i < 8; i++)
                #pragma unroll
                for (int j = 0; j < 8; j++)
                    acc[i][j] += av[i] * bv[j];
        }
        __syncthreads();
    }

    #pragma unroll
    for (int i = 0; i < 8; i++) {
        int r = row0 + rm + i;
        long outrow;
        if (Lrow != Lpad) { int bb = r / Lrow; outrow = (long)bb * Lpad + (r - bb * Lrow); }
        else outrow = r;
        float* Cp = C + outrow * (long)N + col0 + rn;
        float v[8];
        #pragma unroll
        for (int j = 0; j < 8; j++) {
            float t = acc[i][j];
            if (bias) t += bias[col0 + rn + j];
            if (act == 1) t = gelu_f(t);
            v[j] = t;
        }
        *(float4*)Cp       = make_float4(v[0], v[1], v[2], v[3]);
        *(float4*)(Cp + 4) = make_float4(v[4], v[5], v[6], v[7]);
    }
}

// circular conv (width 3, wrap) embedding + mark projection
__global__ void k_embed(const float* __restrict__ x, const float* __restrict__ mark,
                        const float* __restrict__ Wc, const float* __restrict__ Wm,
                        float* __restrict__ out, int L, long n)
{
    long i = (long)blockIdx.x * blockDim.x + threadIdx.x;
    if (i >= n) return;
    int o = (int)(i & 511);
    long bt = i >> 9;
    int t = (int)(bt % L), b = (int)(bt / L);
    int tm = (t == 0) ? (L - 1) : (t - 1);
    int tp = (t == L - 1) ? 0 : (t + 1);
    const float* xb = x + (long)b * L * NC;
    float acc = 0.f;
    #pragma unroll
    for (int c = 0; c < NC; c++) {
        acc += xb[(long)tm * NC + c] * Wc[(0*NC + c) * ND + o];
        acc += xb[(long)t  * NC + c] * Wc[(1*NC + c) * ND + o];
        acc += xb[(long)tp * NC + c] * Wc[(2*NC + c) * ND + o];
    }
    const float* mb = mark + ((long)b * L + t) * NM;
    #pragma unroll
    for (int m = 0; m < NM; m++) acc += mb[m] * Wm[m * ND + o];
    out[i] = acc;
}

__global__ void k_add(const float* __restrict__ a, const float* __restrict__ b,
                      float* __restrict__ o, long n)
{
    long i = (long)blockIdx.x * blockDim.x + threadIdx.x;
    if (i < n) o[i] = a[i] + b[i];
}

// 25-tap moving-average series decomposition with edge clamp.
// mode 0: seasonal only. 1: also store trend. 2: also accumulate trend.
__global__ void k_decomp(const float* __restrict__ in, float* __restrict__ seas,
                         float* __restrict__ trend, int L, int mode, long n)
{
    long i = (long)blockIdx.x * blockDim.x + threadIdx.x;
    if (i >= n) return;
    int d = (int)(i & 511);
    long bt = i >> 9;
    int t = (int)(bt % L), b = (int)(bt / L);
    const float* col = in + (long)b * L * ND + d;
    float s = 0.f;
    #pragma unroll
    for (int j = -12; j <= 12; j++) {
        int tt = t + j;
        tt = tt < 0 ? 0 : (tt > L - 1 ? L - 1 : tt);
        s += col[(long)tt * ND];
    }
    s *= (1.f / 25.f);
    seas[i] = in[i] - s;
    if (mode == 1)      trend[i]  = s;
    else if (mode == 2) trend[i] += s;
}

__global__ void k_zerorows(float* __restrict__ P, int r0, int r1, long n)
{
    long i = (long)blockIdx.x * blockDim.x + threadIdx.x;
    if (i >= n) return;
    int d = (int)(i & 511);
    long br = i >> 9;
    int nr = r1 - r0;
    int r = (int)(br % nr), b = (int)(br / nr);
    P[((long)b * L_P + r0 + r) * ND + d] = 0.f;
}

// corr[b,tau] = (1/512) * sum_m G[b, m, (m - tau) mod L]
__global__ void k_diag(const float* __restrict__ G, float* __restrict__ corr, int L, int Gs)
{
    int b = blockIdx.x, tau = threadIdx.x;
    if (tau >= L) return;
    const float* Gb = G + (long)b * Gs * Gs;
    float acc = 0.f;
    int s = (tau == 0) ? 0 : (L - tau);
    for (int m = 0; m < L; m++) {
        acc += Gb[(long)m * Gs + s];
        if (++s == L) s = 0;
    }
    corr[b * L_P + tau] = acc * (1.f / 512.f);
}

// per-batch top-k + softmax (first-occurrence tie-break, like lax.top_k)
__global__ void k_topk(const float* __restrict__ corr, int L, int ktop,
                       float* __restrict__ wout, int* __restrict__ dout)
{
    int b = blockIdx.x, tid = threadIdx.x;
    __shared__ float sv[L_P];
    __shared__ float rv[256];
    __shared__ int   ri[256];
    __shared__ float topv[24];
    __shared__ int   topi[24];
    for (int i = tid; i < L; i += 256) sv[i] = corr[b * L_P + i];
    __syncthreads();
    for (int kk = 0; kk < ktop; kk++) {
        float best = -1e30f; int bi = 0x7fffffff;
        for (int i = tid; i < L; i += 256) {
            float v = sv[i];
            if (v > best) { best = v; bi = i; }
        }
        rv[tid] = best; ri[tid] = bi;
        __syncthreads();
        for (int s = 128; s > 0; s >>= 1) {
            if (tid < s) {
                if (rv[tid + s] > rv[tid] ||
                    (rv[tid + s] == rv[tid] && ri[tid + s] < ri[tid])) {
                    rv[tid] = rv[tid + s]; ri[tid] = ri[tid + s];
                }
            }
            __syncthreads();
        }
        if (tid == 0) { topv[kk] = rv[0]; topi[kk] = ri[0]; sv[ri[0]] = -1e30f; }
        __syncthreads();
    }
    if (tid == 0) {
        float mx = topv[0], ssum = 0.f;
        for (int i = 0; i < ktop; i++) { float e = expf(topv[i] - mx); topv[i] = e; ssum += e; }
        float inv = 1.f / ssum;
        for (int i = 0; i < ktop; i++) { wout[b*24 + i] = topv[i]*inv; dout[b*24 + i] = topi[i]; }
    }
}

// agg[b,t,:] = sum_i w[b,i] * V[b, (t+delay[b,i]) mod L, :]
__global__ void k_agg(const float* __restrict__ V, const float* __restrict__ w,
                      const int* __restrict__ dl, int ktop, int L, int Lpad,
                      float* __restrict__ out)
{
    int b = blockIdx.x / L, t = blockIdx.x % L;
    __shared__ float sw[24];
    __shared__ int   sd[24];
    if ((int)threadIdx.x < ktop) { sw[threadIdx.x] = w[b*24 + threadIdx.x]; sd[threadIdx.x] = dl[b*24 + threadIdx.x]; }
    __syncthreads();
    const float4* Vb = (const float4*)(V + (long)b * Lpad * ND);
    float4 acc = make_float4(0.f, 0.f, 0.f, 0.f);
    for (int i = 0; i < ktop; i++) {
        int r = t + sd[i]; if (r >= L) r -= L;
        float4 v = Vb[(long)r * 128 + threadIdx.x];
        float wi = sw[i];
        acc.x += wi*v.x; acc.y += wi*v.y; acc.z += wi*v.z; acc.w += wi*v.w;
    }
    ((float4*)out)[((long)b * L + t) * 128 + threadIdx.x] = acc;
}

// layernorm over last dim (512)
__global__ void k_ln(const float* __restrict__ x, const float* __restrict__ g,
                     const float* __restrict__ be, float* __restrict__ out)
{
    long r = blockIdx.x;
    int tid = threadIdx.x;
    const float* xr = x + r * ND;
    float v0 = xr[tid], v1 = xr[tid + 256];
    __shared__ float sh[256];
    sh[tid] = v0 + v1; __syncthreads();
    for (int s = 128; s > 0; s >>= 1) { if (tid < s) sh[tid] += sh[tid + s]; __syncthreads(); }
    float mu = sh[0] * (1.f / 512.f);
    __syncthreads();
    float d0 = v0 - mu, d1 = v1 - mu;
    sh[tid] = d0*d0 + d1*d1; __syncthreads();
    for (int s = 128; s > 0; s >>= 1) { if (tid < s) sh[tid] += sh[tid + s]; __syncthreads(); }
    float rs = rsqrtf(sh[0] * (1.f / 512.f) + 1e-5f);
    out[r * ND + tid]       = d0 * rs * g[tid]       + be[tid];
    out[r * ND + tid + 256] = d1 * rs * g[tid + 256] + be[tid + 256];
}

__global__ void k_colmean(const float* __restrict__ x, float* __restrict__ cm, int L)
{
    int b = blockIdx.x;
    int d = blockIdx.y * 256 + threadIdx.x;
    const float* xb = x + (long)b * L * ND + d;
    float s = 0.f;
    for (int t = 0; t < L; t++) s += xb[(long)t * ND];
    cm[b * ND + d] = s / (float)L;
}

__global__ void k_sub(const float* __restrict__ a, const float* __restrict__ cm,
                      float* __restrict__ o, int L, long n)
{
    long i = (long)blockIdx.x * blockDim.x + threadIdx.x;
    if (i >= n) return;
    int d = (int)(i & 511);
    int b = (int)(i / ((long)L * ND));
    o[i] = a[i] - cm[b * ND + d];
}

__global__ void k_meanenc(const float* __restrict__ x, float* __restrict__ mean)
{
    int tid = threadIdx.x;
    if (tid >= NB * NC) return;
    int b = tid / NC, c = tid % NC;
    const float* xb = x + (long)b * L_E * NC + c;
    float s = 0.f;
    for (int t = 0; t < L_E; t++) s += xb[(long)t * NC];
    mean[b * 8 + c] = s * (1.f / 512.f);
}

// seasonal_init / trend_init for the decoder
__global__ void k_decinit(const float* __restrict__ x, const float* __restrict__ mean,
                          float* __restrict__ SI, float* __restrict__ TI, long n)
{
    long i = (long)blockIdx.x * blockDim.x + threadIdx.x;
    if (i >= n) return;
    int c = (int)(i % NC);
    long bt = i / NC;
    int t = (int)(bt % L_D), b = (int)(bt / L_D);
    if (t < LABEL) {
        int te = LABEL + t;
        const float* col = x + (long)b * L_E * NC + c;
        float s = 0.f;
        #pragma unroll
        for (int j = -12; j <= 12; j++) {
            int tt = te + j;
            tt = tt < 0 ? 0 : (tt > L_E - 1 ? L_E - 1 : tt);
            s += col[(long)tt * NC];
        }
        s *= (1.f / 25.f);
        TI[i] = s;
        SI[i] = col[(long)te * NC] - s;
    } else {
        TI[i] = mean[b * 8 + c];
        SI[i] = 0.f;
    }
}

__global__ void k_markdec(const float* __restrict__ me, const float* __restrict__ md,
                          float* __restrict__ out, long n)
{
    long i = (long)blockIdx.x * blockDim.x + threadIdx.x;
    if (i >= n) return;
    int m = (int)(i & 3);
    long bt = i >> 2;
    int t = (int)(bt % L_D), b = (int)(bt / L_D);
    out[i] = (t < LABEL) ? me[((long)b * L_E + LABEL + t) * NM + m]
                         : md[((long)b * PRED + (t - LABEL)) * NM + m];
}

// out = trend_init + circconv(TR, W_trend) + xln @ Wproj + bproj, last PRED steps
__global__ void k_final(const float* __restrict__ xln, const float* __restrict__ TR,
                        const float* __restrict__ TI, const float* __restrict__ Wt,
                        const float* __restrict__ Wp, const float* __restrict__ bp,
                        float* __restrict__ out, long n)
{
    long i = (long)blockIdx.x * blockDim.x + threadIdx.x;
    if (i >= n) return;
    int c = (int)(i % NC);
    long bt = i / NC;
    int t = (int)(bt % PRED), b = (int)(bt / PRED);
    int tt = LABEL + t;
    float tr = TI[((long)b * L_D + tt) * NC + c];
    #pragma unroll
    for (int w = 0; w < 3; w++) {
        int r = tt - 1 + w;
        if (r < 0) r += L_D;
        if (r >= L_D) r -= L_D;
        const float* TRr = TR + ((long)b * L_D + r) * ND;
        const float* Wtr = Wt + (long)w * ND * NC + c;
        float a = 0.f;
        for (int cc = 0; cc < ND; cc++) a += TRr[cc] * Wtr[cc * NC];
        tr += a;
    }
    float se = bp[c];
    const float* xr = xln + ((long)b * L_D + tt) * ND;
    for (int d = 0; d < ND; d++) se += xr[d] * Wp[d * NC + c];
    out[i] = tr + se;
}

static inline void launch_gemm(const float* A, const float* Bm, const float* bias, float* C,
                               int M, int N, int K, int transB, int act,
                               int Lrow, int Lpad, long sA, long sB, long sC, int batch)
{
    dim3 grid(N / 128, M / 128, batch);
    k_gemm<<<grid, 256>>>(A, Bm, bias, C, M, N, K, transB, act, Lrow, Lpad, sA, sB, sC);
}

#define FLATG(n) (int)(((n) + 255) / 256), 256

extern "C" void kernel_launch(void* const* d_in, const int* in_sizes, int n_in,
                              void* d_out, int out_size)
{
    const float* x_enc      = (const float*)d_in[0];
    const float* x_mark_enc = (const float*)d_in[1];
    const float* x_mark_dec = (const float*)d_in[3];
    const float* W_enc_emb  = (const float*)d_in[4];
    const float* W_mark_enc = (const float*)d_in[5];
    const float* W_dec_emb  = (const float*)d_in[6];
    const float* W_mark_dec = (const float*)d_in[7];
    const float* eW_attn    = (const float*)d_in[8];
    const float* eb_attn    = (const float*)d_in[9];
    const float* eW1        = (const float*)d_in[10];
    const float* eW2        = (const float*)d_in[11];
    const float* eg         = (const float*)d_in[12];
    const float* ebeta      = (const float*)d_in[13];
    const float* sW         = (const float*)d_in[14];
    const float* sb         = (const float*)d_in[15];
    const float* cW         = (const float*)d_in[16];
    const float* cb         = (const float*)d_in[17];
    const float* dW1        = (const float*)d_in[18];
    const float* dW2        = (const float*)d_in[19];
    const float* W_trend    = (const float*)d_in[20];
    const float* dg         = (const float*)d_in[21];
    const float* dbeta      = (const float*)d_in[22];
    const float* Wproj      = (const float*)d_in[23];
    const float* bproj      = (const float*)d_in[24];
    float* out = (float*)d_out;

    float *X, *A_, *Q, *Kb, *V, *G, *H, *E, *TR, *LN, *SI, *TI, *MD, *MEAN, *CORR, *WT, *CM;
    int* DLY;
    cudaGetSymbolAddress((void**)&X,   g_X);
    cudaGetSymbolAddress((void**)&A_,  g_A);
    cudaGetSymbolAddress((void**)&Q,   g_Q);
    cudaGetSymbolAddress((void**)&Kb,  g_K);
    cudaGetSymbolAddress((void**)&V,   g_V);
    cudaGetSymbolAddress((void**)&G,   g_G);
    cudaGetSymbolAddress((void**)&H,   g_H);
    cudaGetSymbolAddress((void**)&E,   g_E);
    cudaGetSymbolAddress((void**)&TR,  g_TR);
    cudaGetSymbolAddress((void**)&LN,  g_LN);
    cudaGetSymbolAddress((void**)&SI,  g_SI);
    cudaGetSymbolAddress((void**)&TI,  g_TI);
    cudaGetSymbolAddress((void**)&MD,  g_MD);
    cudaGetSymbolAddress((void**)&MEAN,g_MEAN);
    cudaGetSymbolAddress((void**)&CORR,g_CORR);
    cudaGetSymbolAddress((void**)&WT,  g_WT);
    cudaGetSymbolAddress((void**)&CM,  g_CM);
    cudaGetSymbolAddress((void**)&DLY, g_DLY);

    const long nE = (long)NB * L_E * ND;
    const long nD = (long)NB * L_D * ND;

    // ===== encoder embedding =====
    k_embed<<<FLATG(nE)>>>(x_enc, x_mark_enc, W_enc_emb, W_mark_enc, X, L_E, nE);

    // ===== encoder layers =====
    for (int l = 0; l < 2; l++) {
        const float* W  = eW_attn + (size_t)l * 4 * ND * ND;
        const float* bb = eb_attn + (size_t)l * 4 * ND;
        launch_gemm(X, W + 0*ND*ND, bb + 0*ND, Q,  NB*L_E, ND, ND, 0, 0, L_E, L_E, 0,0,0, 1);
        launch_gemm(X, W + 1*ND*ND, bb + 1*ND, Kb, NB*L_E, ND, ND, 0, 0, L_E, L_E, 0,0,0, 1);
        launch_gemm(X, W + 2*ND*ND, bb + 2*ND, V,  NB*L_E, ND, ND, 0, 0, L_E, L_E, 0,0,0, 1);
        launch_gemm(Q, Kb, nullptr, G, L_E, L_E, ND, 1, 0, L_E, L_E,
                    (long)L_E*ND, (long)L_E*ND, (long)L_E*L_E, NB);
        k_diag<<<NB, L_P>>>(G, CORR, L_E, L_E);
        k_topk<<<NB, 256>>>(CORR, L_E, KTOP_E, WT, DLY);
        k_agg<<<NB * L_E, 128>>>(V, WT, DLY, KTOP_E, L_E, L_E, A_);
        launch_gemm(A_, W + 3*ND*ND, bb + 3*ND, H, NB*L_E, ND, ND, 0, 0, L_E, L_E, 0,0,0, 1);
        k_add<<<FLATG(nE)>>>(X, H, A_, nE);
        k_decomp<<<FLATG(nE)>>>(A_, X, (float*)nullptr, L_E, 0, nE);
        launch_gemm(X, eW1 + (size_t)l*ND*NDFF,  nullptr, H,  NB*L_E, NDFF, ND,   0, 1, L_E, L_E, 0,0,0, 1);
        launch_gemm(H, eW2 + (size_t)l*NDFF*ND,  nullptr, A_, NB*L_E, ND,   NDFF, 0, 0, L_E, L_E, 0,0,0, 1);
        k_add<<<FLATG(nE)>>>(X, A_, A_, nE);
        k_decomp<<<FLATG(nE)>>>(A_, X, (float*)nullptr, L_E, 0, nE);
    }

    // ===== encoder layernorm (with time-mean subtraction) =====
    k_ln<<<NB * L_E, 256>>>(X, eg, ebeta, E);
    k_colmean<<<dim3(NB, 2), 256>>>(E, CM, L_E);
    k_sub<<<FLATG(nE)>>>(E, CM, E, L_E, nE);

    // ===== decoder init =====
    k_meanenc<<<1, 256>>>(x_enc, MEAN);
    k_decinit<<<FLATG((long)NB*L_D*NC)>>>(x_enc, MEAN, SI, TI, (long)NB*L_D*NC);
    k_markdec<<<FLATG((long)NB*L_D*NM)>>>(x_mark_enc, x_mark_dec, MD, (long)NB*L_D*NM);
    k_embed<<<FLATG(nD)>>>(SI, MD, W_dec_emb, W_mark_dec, X, L_D, nD);

    // ===== decoder self-attention =====
    launch_gemm(X, sW + 0*ND*ND, sb + 0*ND, Q,  NB*L_D, ND, ND, 0, 0, L_D, L_P, 0,0,0, 1);
    launch_gemm(X, sW + 1*ND*ND, sb + 1*ND, Kb, NB*L_D, ND, ND, 0, 0, L_D, L_P, 0,0,0, 1);
    launch_gemm(X, sW + 2*ND*ND, sb + 2*ND, V,  NB*L_D, ND, ND, 0, 0, L_D, L_P, 0,0,0, 1);
    launch_gemm(Q, Kb, nullptr, G, L_P, L_P, ND, 1, 0, L_P, L_P,
                (long)L_P*ND, (long)L_P*ND, (long)L_P*L_P, NB);
    k_diag<<<NB, L_P>>>(G, CORR, L_D, L_P);
    k_topk<<<NB, 256>>>(CORR, L_D, KTOP_D, WT, DLY);
    k_agg<<<NB * L_D, 128>>>(V, WT, DLY, KTOP_D, L_D, L_P, A_);
    launch_gemm(A_, sW + 3*ND*ND, sb + 3*ND, H, NB*L_D, ND, ND, 0, 0, L_D, L_D, 0,0,0, 1);
    k_add<<<FLATG(nD)>>>(X, H, A_, nD);
    k_decomp<<<FLATG(nD)>>>(A_, X, TR, L_D, 1, nD);

    // ===== decoder cross-attention (K/V from enc_out, zero-padded 512->592) =====
    launch_gemm(X, cW + 0*ND*ND, cb + 0*ND, Q,  NB*L_D, ND, ND, 0, 0, L_D, L_P, 0,0,0, 1);
    launch_gemm(E, cW + 1*ND*ND, cb + 1*ND, Kb, NB*L_E, ND, ND, 0, 0, L_E, L_P, 0,0,0, 1);
    launch_gemm(E, cW + 2*ND*ND, cb + 2*ND, V,  NB*L_E, ND, ND, 0, 0, L_E, L_P, 0,0,0, 1);
    {
        long nz = (long)NB * (L_D - L_E) * ND;
        k_zerorows<<<FLATG(nz)>>>(Kb, L_E, L_D, nz);
        k_zerorows<<<FLATG(nz)>>>(V,  L_E, L_D, nz);
    }
    launch_gemm(Q, Kb, nullptr, G, L_P, L_P, ND, 1, 0, L_P, L_P,
                (long)L_P*ND, (long)L_P*ND, (long)L_P*L_P, NB);
    k_diag<<<NB, L_P>>>(G, CORR, L_D, L_P);
    k_topk<<<NB, 256>>>(CORR, L_D, KTOP_D, WT, DLY);
    k_agg<<<NB * L_D, 128>>>(V, WT, DLY, KTOP_D, L_D, L_P, A_);
    launch_gemm(A_, cW + 3*ND*ND, cb + 3*ND, H, NB*L_D, ND, ND, 0, 0, L_D, L_D, 0,0,0, 1);
    k_add<<<FLATG(nD)>>>(X, H, A_, nD);
    k_decomp<<<FLATG(nD)>>>(A_, X, TR, L_D, 2, nD);

    // ===== decoder FFN =====
    launch_gemm(X, dW1, nullptr, H,  NB*L_D, NDFF, ND,   0, 1, L_D, L_D, 0,0,0, 1);
    launch_gemm(H, dW2, nullptr, A_, NB*L_D, ND,   NDFF, 0, 0, L_D, L_D, 0,0,0, 1);
    k_add<<<FLATG(nD)>>>(X, A_, A_, nD);
    k_decomp<<<FLATG(nD)>>>(A_, X, TR, L_D, 2, nD);

    // ===== decoder layernorm + final output =====
    k_ln<<<NB * L_D, 256>>>(X, dg, dbeta, LN);
    k_colmean<<<dim3(NB, 2), 256>>>(LN, CM, L_D);
    k_sub<<<FLATG(nD)>>>(LN, CM, LN, L_D, nD);

    long nOut = (long)NB * PRED * NC;
    k_final<<<FLATG(nOut)>>>(LN, TR, TI, W_trend, Wproj, bproj, out, nOut);
}